// round 6
// baseline (speedup 1.0000x reference)
#include <cuda_runtime.h>
#include <stdint.h>

// ============================================================================
// ControlPointBetaNoise — exact re-implementation of the JAX reference.
// R5: (a) MUFU-pressure trim (rsqrtf for c, __fdividef/__expf on paths that
// cannot flip accept decisions), (b) single merged retry loop for all four
// gamma samples with warp-vote section guards, (c) two pixels per thread
// (shared bicubic row-dots) for 4-way threefry ILP.
// Accept-test arithmetic (logf etc.) kept bit-compatible with the passing R2.
// ============================================================================

static const unsigned B_ = 32, C_ = 3, H_ = 512, W_ = 512;
static const unsigned PIX_PER_IMG = H_ * W_;   // 262144
static const unsigned HALF_PIX = PIX_PER_IMG / 2;  // 131072

struct U2 { uint32_t a, b; };

__host__ __device__ __forceinline__ uint32_t rotl32(uint32_t x, int r) {
#ifdef __CUDA_ARCH__
  return __funnelshift_l(x, x, r);
#else
  return (x << r) | (x >> (32 - r));
#endif
}

// threefry2x32, 20 rounds — matches jax._src.prng.threefry2x32 exactly.
__host__ __device__ __forceinline__ U2 tf2x32(uint32_t k0, uint32_t k1,
                                              uint32_t x0, uint32_t x1) {
  uint32_t ks2 = k0 ^ k1 ^ 0x1BD11BDAu;
  x0 += k0; x1 += k1;
#define TF_RND(r) { x0 += x1; x1 = rotl32(x1, (r)); x1 ^= x0; }
  TF_RND(13) TF_RND(15) TF_RND(26) TF_RND(6)
  x0 += k1;  x1 += ks2 + 1u;
  TF_RND(17) TF_RND(29) TF_RND(16) TF_RND(24)
  x0 += ks2; x1 += k0 + 2u;
  TF_RND(13) TF_RND(15) TF_RND(26) TF_RND(6)
  x0 += k0;  x1 += k1 + 3u;
  TF_RND(17) TF_RND(29) TF_RND(16) TF_RND(24)
  x0 += k1;  x1 += ks2 + 4u;
  TF_RND(13) TF_RND(15) TF_RND(26) TF_RND(6)
  x0 += ks2; x1 += k0 + 5u;
#undef TF_RND
  return U2{x0, x1};
}

// scalar-shape random_bits(key, 32, ())  [partitionable threefry]
__device__ __forceinline__ uint32_t bits_scalar(uint32_t k0, uint32_t k1) {
  U2 r = tf2x32(k0, k1, 0u, 0u);
  return r.a ^ r.b;
}

// uniform [0,1): bitcast((bits>>9)|0x3f800000) - 1.0  (matches jax._uniform)
__device__ __forceinline__ float u01_from_bits(uint32_t bits) {
  return __uint_as_float((bits >> 9) | 0x3F800000u) - 1.0f;
}

// XLA f32 erf_inv (Giles polynomial) — what lax.erf_inv lowers to.
__device__ __forceinline__ float erfinv_f32(float x) {
  float w = -log1pf(-x * x);
  float p;
  if (w < 5.0f) {
    w -= 2.5f;
    p = 2.81022636e-08f;
    p = fmaf(p, w, 3.43273939e-07f);
    p = fmaf(p, w, -3.5233877e-06f);
    p = fmaf(p, w, -4.39150654e-06f);
    p = fmaf(p, w, 0.00021858087f);
    p = fmaf(p, w, -0.00125372503f);
    p = fmaf(p, w, -0.00417768164f);
    p = fmaf(p, w, 0.246640727f);
    p = fmaf(p, w, 1.50140941f);
  } else {
    w = sqrtf(w) - 3.0f;
    p = -0.000200214257f;
    p = fmaf(p, w, 0.000100950558f);
    p = fmaf(p, w, 0.00134934322f);
    p = fmaf(p, w, -0.00367342844f);
    p = fmaf(p, w, 0.00573950773f);
    p = fmaf(p, w, -0.0076224613f);
    p = fmaf(p, w, 0.00943887047f);
    p = fmaf(p, w, 1.00167406f);
    p = fmaf(p, w, 2.83297682f);
  }
  return p * x;
}

// jax.random.normal: u = uniform(key, lo=nextafter(-1,0), hi=1); sqrt(2)*erfinv(u)
__device__ __forceinline__ float normal_from_key(uint32_t k0, uint32_t k1) {
  uint32_t bits = bits_scalar(k0, k1);
  float f = u01_from_bits(bits);
  const float LO = __uint_as_float(0xBF7FFFFFu);  // nextafter(-1,0)
  float u = fmaxf(LO, f * 2.0f + LO);
  return 1.41421356237f * erfinv_f32(u);
}

// ---------------------------------------------------------------------------
// Bicubic weight table: jax.image.resize "bicubic" (Keys a=-0.5, renormalized,
// half-pixel sampling). Identical for H and W (8 -> 512).
// ---------------------------------------------------------------------------
__device__ float g_w[512][8];

__global__ void weights_kernel() {
  int j = threadIdx.x;  // 0..511
  float s = (j + 0.5f) * (1.0f / 64.0f) - 0.5f;
  float w[8]; float sum = 0.0f;
#pragma unroll
  for (int i = 0; i < 8; i++) {
    float x = fabsf(s - (float)i);
    float out = ((1.5f * x - 2.5f) * x) * x + 1.0f;
    if (x >= 1.0f) out = ((-0.5f * x + 2.5f) * x - 4.0f) * x + 2.0f;
    if (x >= 2.0f) out = 0.0f;
    w[i] = out; sum += out;
  }
#pragma unroll
  for (int i = 0; i < 8; i++) g_w[j][i] = w[i] / sum;
}

// ---------------------------------------------------------------------------
// Marsaglia–Tsang gamma-sampler state and steps (lazy key advancement).
// ---------------------------------------------------------------------------
struct GS {
  uint32_t kl0, kl1, xk0, xk1;
  float x, v, U, d, c, logV;
};

// Accept test on the current attempt. Precondition handled inside (v<=0 ->
// not accepted; triggers an inner redraw in the next step). Arithmetic is
// identical to the passing R2/R4 kernels (accurate logf — decision-critical).
__device__ __forceinline__ bool mt_try(GS& g) {
  if (g.v <= 0.0f) return false;
  float X = g.x * g.x;
  float V = (g.v * g.v) * g.v;
  float lV = logf(V);
  bool rej = (g.U >= 1.0f - 0.0331f * (X * X)) &&
             (logf(g.U) >= 0.5f * X + g.d * (1.0f - V + lV));
  g.logV = lV;
  return !rej;
}

// First attempt. key chain: ek = TF(K,(0,e)); kc = TF(ek,(0,0));
// xk = TF(kc,(0,1)); Uk = TF(kc,(0,2)); sub = TF(xk,(0,1)).
__device__ __forceinline__ bool g_init(GS& g, uint32_t K0, uint32_t K1,
                                       uint32_t e, float alpha) {
  g.d = alpha - (1.0f / 3.0f);
  g.c = (1.0f / 3.0f) * rsqrtf(g.d);     // was (1/3)/sqrtf(d): saves 1 RCP
  U2 ek = tf2x32(K0, K1, 0u, e);
  U2 kc = tf2x32(ek.a, ek.b, 0u, 0u);
  g.kl0 = kc.a; g.kl1 = kc.b;
  U2 xk = tf2x32(kc.a, kc.b, 0u, 1u);
  g.xk0 = xk.a; g.xk1 = xk.b;
  U2 Uk = tf2x32(kc.a, kc.b, 0u, 2u);
  U2 sb = tf2x32(xk.a, xk.b, 0u, 1u);
  g.x = normal_from_key(sb.a, sb.b);
  g.v = fmaf(g.c, g.x, 1.0f);
  g.U = u01_from_bits(bits_scalar(Uk.a, Uk.b));
  g.logV = 0.0f;
  return mt_try(g);
}

// One retry step: inner redraw if v<=0, else full outer retry. Keys advanced
// lazily exactly as in the JAX while_loop chain.
__device__ __forceinline__ bool g_step(GS& g) {
  if (g.v <= 0.0f) {
    U2 nxt = tf2x32(g.xk0, g.xk1, 0u, 0u);
    g.xk0 = nxt.a; g.xk1 = nxt.b;
    U2 sb = tf2x32(g.xk0, g.xk1, 0u, 1u);
    g.x = normal_from_key(sb.a, sb.b);
    g.v = fmaf(g.c, g.x, 1.0f);
  } else {
    U2 nk = tf2x32(g.kl0, g.kl1, 0u, 0u);
    g.kl0 = nk.a; g.kl1 = nk.b;
    U2 xk = tf2x32(g.kl0, g.kl1, 0u, 1u);
    g.xk0 = xk.a; g.xk1 = xk.b;
    U2 Uk = tf2x32(g.kl0, g.kl1, 0u, 2u);
    U2 sb = tf2x32(xk.a, xk.b, 0u, 1u);
    g.x = normal_from_key(sb.a, sb.b);
    g.v = fmaf(g.c, g.x, 1.0f);
    g.U = u01_from_bits(bits_scalar(Uk.a, Uk.b));
  }
  return mt_try(g);
}

// ---------------------------------------------------------------------------
// Main kernel: two pixels per thread (same column, rows y and y+256).
// ---------------------------------------------------------------------------
__global__ void __launch_bounds__(256)
beta_noise_kernel(const float* __restrict__ mcp, float* __restrict__ out,
                  uint32_t ka0, uint32_t ka1, uint32_t kb0, uint32_t kb1) {
  __shared__ float G[64];
  unsigned bc = blockIdx.y;
  if (threadIdx.x < 64)
    G[threadIdx.x] = mcp[bc * 64u + threadIdx.x] * 0.9f + 0.05f;
  __syncthreads();

  unsigned pix = blockIdx.x * 256u + threadIdx.x;   // [0, 131072)
  unsigned y1 = pix >> 9, x = pix & 511u;
  unsigned y2 = y1 + 256u;

  // column dots gy[i] = <wx, G_row_i> — shared by both pixels (same x)
  const float4* wx4 = reinterpret_cast<const float4*>(g_w[x]);
  float4 wxa = wx4[0], wxb = wx4[1];
  float gy[8];
#pragma unroll
  for (int i = 0; i < 8; i++) {
    const float* gr = &G[i * 8];
    gy[i] = wxa.x * gr[0] + wxa.y * gr[1] + wxa.z * gr[2] + wxa.w * gr[3]
          + wxb.x * gr[4] + wxb.y * gr[5] + wxb.z * gr[6] + wxb.w * gr[7];
  }

  auto mix_row = [&](unsigned yy) -> float {
    const float4* wy4 = reinterpret_cast<const float4*>(g_w[yy]);
    float4 a = wy4[0], b = wy4[1];
    return a.x * gy[0] + a.y * gy[1] + a.z * gy[2] + a.w * gy[3]
         + b.x * gy[4] + b.y * gy[5] + b.z * gy[6] + b.w * gy[7];
  };
  float m1 = fminf(fmaxf(mix_row(y1), 0.05f), 0.95f);
  float m2 = fminf(fmaxf(mix_row(y2), 0.05f), 0.95f);

  auto params = [](float m, float& A, float& Bt) {
    float t = m * (1.0f - m);
    float sd = t - 1e-6f;
    float Vv = __fdividef(t, sd * sd) - 1.0f;
    A  = fmaxf(m * Vv, 0.0f) + 1e-6f;           // always >= 1.0027
    Bt = fmaxf((1.0f - m) * Vv, 0.0f) + 1e-6f;  // always >= 1.0027
  };
  float A1, Bt1, A2, Bt2;
  params(m1, A1, Bt1);
  params(m2, A2, Bt2);

  unsigned e1 = bc * PIX_PER_IMG + pix;
  unsigned e2 = e1 + HALF_PIX;

  // -------- four interleaved first attempts (ILP across TF chains) --------
  GS a1, b1, a2, b2;
  bool da1 = g_init(a1, ka0, ka1, e1, A1);
  bool db1 = g_init(b1, kb0, kb1, e1, Bt1);
  bool da2 = g_init(a2, ka0, ka1, e2, A2);
  bool db2 = g_init(b2, kb0, kb1, e2, Bt2);

  // -------- single merged retry loop, warp-vote guarded sections ----------
  for (;;) {
    bool na1 = !da1, nb1 = !db1, na2 = !da2, nb2 = !db2;
    if (!__any_sync(0xFFFFFFFFu, na1 | nb1 | na2 | nb2)) break;
    if (__any_sync(0xFFFFFFFFu, na1)) { if (na1) da1 = g_step(a1); }
    if (__any_sync(0xFFFFFFFFu, nb1)) { if (nb1) db1 = g_step(b1); }
    if (__any_sync(0xFFFFFFFFu, na2)) { if (na2) da2 = g_step(a2); }
    if (__any_sync(0xFFFFFFFFu, nb2)) { if (nb2) db2 = g_step(b2); }
  }

  // beta = 1/(1+exp(lgb-lga));  lgb-lga = log(db/da) + logVb - logVa
  // (output-only arithmetic: fast intrinsics are safe here)
  float z1 = logf(__fdividef(b1.d, a1.d)) + (b1.logV - a1.logV);
  float z2 = logf(__fdividef(b2.d, a2.d)) + (b2.logV - a2.logV);
  out[e1] = __fdividef(1.0f, 1.0f + __expf(z1));
  out[e2] = __fdividef(1.0f, 1.0f + __expf(z2));
}

// ---------------------------------------------------------------------------
extern "C" void kernel_launch(void* const* d_in, const int* in_sizes, int n_in,
                              void* d_out, int out_size) {
  // find mean_control_points by size (32*3*8*8 = 6144)
  const float* mcp = (const float*)d_in[1];
  for (int i = 0; i < n_in; i++)
    if (in_sizes[i] == 6144) { mcp = (const float*)d_in[i]; break; }

  // root key = threefry_seed(1234) = (0, 1234); key_a, key_b = split(root)
  U2 ka = tf2x32(0u, 1234u, 0u, 0u);
  U2 kb = tf2x32(0u, 1234u, 0u, 1u);

  weights_kernel<<<1, 512>>>();
  dim3 grid(HALF_PIX / 256, B_ * C_);
  beta_noise_kernel<<<grid, 256>>>(mcp, (float*)d_out,
                                   ka.a, ka.b, kb.a, kb.b);
}

// round 7
// speedup vs baseline: 1.1740x; 1.1740x over previous
#include <cuda_runtime.h>
#include <stdint.h>

// ============================================================================
// ControlPointBetaNoise — exact re-implementation of the JAX reference.
// R6 = R4 skeleton (best so far) + safe MUFU trims validated in R5:
//   - rsqrtf for the MT 'c' constant, __fdividef for the V parameter
//   - output-only softmax via single logf(ratio) + __expf + __fdividef
// Accept-test arithmetic (logf of U and V) kept at full precision —
// decision-critical. One pixel per thread, inline continuation loops.
// ============================================================================

static const unsigned B_ = 32, C_ = 3, H_ = 512, W_ = 512;
static const unsigned PIX_PER_IMG = H_ * W_;              // 262144

struct U2 { uint32_t a, b; };

__host__ __device__ __forceinline__ uint32_t rotl32(uint32_t x, int r) {
#ifdef __CUDA_ARCH__
  return __funnelshift_l(x, x, r);
#else
  return (x << r) | (x >> (32 - r));
#endif
}

// threefry2x32, 20 rounds — matches jax._src.prng.threefry2x32 exactly.
__host__ __device__ __forceinline__ U2 tf2x32(uint32_t k0, uint32_t k1,
                                              uint32_t x0, uint32_t x1) {
  uint32_t ks2 = k0 ^ k1 ^ 0x1BD11BDAu;
  x0 += k0; x1 += k1;
#define TF_RND(r) { x0 += x1; x1 = rotl32(x1, (r)); x1 ^= x0; }
  TF_RND(13) TF_RND(15) TF_RND(26) TF_RND(6)
  x0 += k1;  x1 += ks2 + 1u;
  TF_RND(17) TF_RND(29) TF_RND(16) TF_RND(24)
  x0 += ks2; x1 += k0 + 2u;
  TF_RND(13) TF_RND(15) TF_RND(26) TF_RND(6)
  x0 += k0;  x1 += k1 + 3u;
  TF_RND(17) TF_RND(29) TF_RND(16) TF_RND(24)
  x0 += k1;  x1 += ks2 + 4u;
  TF_RND(13) TF_RND(15) TF_RND(26) TF_RND(6)
  x0 += ks2; x1 += k0 + 5u;
#undef TF_RND
  return U2{x0, x1};
}

// scalar-shape random_bits(key, 32, ())  [partitionable threefry]
__device__ __forceinline__ uint32_t bits_scalar(uint32_t k0, uint32_t k1) {
  U2 r = tf2x32(k0, k1, 0u, 0u);
  return r.a ^ r.b;
}

// uniform [0,1): bitcast((bits>>9)|0x3f800000) - 1.0  (matches jax._uniform)
__device__ __forceinline__ float u01_from_bits(uint32_t bits) {
  return __uint_as_float((bits >> 9) | 0x3F800000u) - 1.0f;
}

// XLA f32 erf_inv (Giles polynomial) — what lax.erf_inv lowers to.
__device__ __forceinline__ float erfinv_f32(float x) {
  float w = -log1pf(-x * x);
  float p;
  if (w < 5.0f) {
    w -= 2.5f;
    p = 2.81022636e-08f;
    p = fmaf(p, w, 3.43273939e-07f);
    p = fmaf(p, w, -3.5233877e-06f);
    p = fmaf(p, w, -4.39150654e-06f);
    p = fmaf(p, w, 0.00021858087f);
    p = fmaf(p, w, -0.00125372503f);
    p = fmaf(p, w, -0.00417768164f);
    p = fmaf(p, w, 0.246640727f);
    p = fmaf(p, w, 1.50140941f);
  } else {
    w = sqrtf(w) - 3.0f;
    p = -0.000200214257f;
    p = fmaf(p, w, 0.000100950558f);
    p = fmaf(p, w, 0.00134934322f);
    p = fmaf(p, w, -0.00367342844f);
    p = fmaf(p, w, 0.00573950773f);
    p = fmaf(p, w, -0.0076224613f);
    p = fmaf(p, w, 0.00943887047f);
    p = fmaf(p, w, 1.00167406f);
    p = fmaf(p, w, 2.83297682f);
  }
  return p * x;
}

// jax.random.normal: u = uniform(key, lo=nextafter(-1,0), hi=1); sqrt(2)*erfinv(u)
__device__ __forceinline__ float normal_from_key(uint32_t k0, uint32_t k1) {
  uint32_t bits = bits_scalar(k0, k1);
  float f = u01_from_bits(bits);
  const float LO = __uint_as_float(0xBF7FFFFFu);  // nextafter(-1,0)
  float u = fmaxf(LO, f * 2.0f + LO);
  return 1.41421356237f * erfinv_f32(u);
}

// ---------------------------------------------------------------------------
// Bicubic weight table: jax.image.resize "bicubic" (Keys a=-0.5, renormalized,
// half-pixel sampling). Identical for H and W (8 -> 512).
// ---------------------------------------------------------------------------
__device__ float g_w[512][8];

__global__ void weights_kernel() {
  int j = threadIdx.x;  // 0..511
  float s = (j + 0.5f) * (1.0f / 64.0f) - 0.5f;
  float w[8]; float sum = 0.0f;
#pragma unroll
  for (int i = 0; i < 8; i++) {
    float x = fabsf(s - (float)i);
    float out = ((1.5f * x - 2.5f) * x) * x + 1.0f;
    if (x >= 1.0f) out = ((-0.5f * x + 2.5f) * x - 4.0f) * x + 2.0f;
    if (x >= 2.0f) out = 0.0f;
    w[i] = out; sum += out;
  }
#pragma unroll
  for (int i = 0; i < 8; i++) g_w[j][i] = w[i] / sum;
}

// ---------------------------------------------------------------------------
// Marsaglia–Tsang continuation loop: resumes from an already-computed first
// attempt (outer key kl, inner key xk, draw x/v, uniform U). Lazily advances
// keys only when a retry actually happens — no replayed threefry work.
// Returns log(V) of the accepted draw.
// ---------------------------------------------------------------------------
__device__ __forceinline__ float mt_finish(uint32_t kl0, uint32_t kl1,
                                           uint32_t xk0, uint32_t xk1,
                                           float x, float v, float U,
                                           float d, float c) {
  for (;;) {
    // inner rejection: redraw normal until v > 0 (advance inner key lazily)
    while (v <= 0.0f) {
      U2 nxt = tf2x32(xk0, xk1, 0u, 0u);
      xk0 = nxt.a; xk1 = nxt.b;
      U2 sub = tf2x32(xk0, xk1, 0u, 1u);
      x = normal_from_key(sub.a, sub.b);
      v = fmaf(c, x, 1.0f);
    }
    float X = x * x;
    float V = (v * v) * v;
    float lV = logf(V);            // decision-critical: full precision
    bool rej = (U >= 1.0f - 0.0331f * (X * X)) &&
               (logf(U) >= 0.5f * X + d * (1.0f - V + lV));
    if (!rej) return lV;
    // outer rejection: advance outer key lazily, draw a fresh attempt
    U2 nk = tf2x32(kl0, kl1, 0u, 0u);
    kl0 = nk.a; kl1 = nk.b;
    U2 xk = tf2x32(kl0, kl1, 0u, 1u);
    xk0 = xk.a; xk1 = xk.b;
    U2 Uk = tf2x32(kl0, kl1, 0u, 2u);
    U2 sub = tf2x32(xk0, xk1, 0u, 1u);
    x = normal_from_key(sub.a, sub.b);
    v = fmaf(c, x, 1.0f);
    U = u01_from_bits(bits_scalar(Uk.a, Uk.b));
  }
}

// ---------------------------------------------------------------------------
// Main kernel: one thread per output pixel.
// ---------------------------------------------------------------------------
__global__ void __launch_bounds__(256)
beta_noise_kernel(const float* __restrict__ mcp, float* __restrict__ out,
                  uint32_t ka0, uint32_t ka1, uint32_t kb0, uint32_t kb1) {
  __shared__ float G[64];
  unsigned bc = blockIdx.y;
  if (threadIdx.x < 64)
    G[threadIdx.x] = mcp[bc * 64u + threadIdx.x] * 0.9f + 0.05f;
  __syncthreads();

  unsigned pix = blockIdx.x * 256u + threadIdx.x;
  unsigned y = pix >> 9, x = pix & 511u;

  // separable bicubic: m = wy^T * G * wx
  const float4* wx4 = reinterpret_cast<const float4*>(g_w[x]);
  float4 wxa = wx4[0], wxb = wx4[1];
  const float4* wy4 = reinterpret_cast<const float4*>(g_w[y]);
  float4 wya = wy4[0], wyb = wy4[1];
  float wyv[8] = {wya.x, wya.y, wya.z, wya.w, wyb.x, wyb.y, wyb.z, wyb.w};

  float m = 0.0f;
#pragma unroll
  for (int i = 0; i < 8; i++) {
    const float* gr = &G[i * 8];
    float gy = wxa.x * gr[0] + wxa.y * gr[1] + wxa.z * gr[2] + wxa.w * gr[3]
             + wxb.x * gr[4] + wxb.y * gr[5] + wxb.z * gr[6] + wxb.w * gr[7];
    m += wyv[i] * gy;
  }

  m = fminf(fmaxf(m, 0.05f), 0.95f);
  float t  = m * (1.0f - m);
  float sd = t - 1e-6f;
  float V_ = __fdividef(t, sd * sd) - 1.0f;           // fast div (safe)
  float Alpha = fmaxf(m * V_, 0.0f) + 1e-6f;          // always >= 1.0027
  float Beta  = fmaxf((1.0f - m) * V_, 0.0f) + 1e-6f; // always >= 1.0027

  // MT constants (boost branch provably dead: alpha >= 1)
  float da = Alpha - (1.0f / 3.0f);
  float ca = (1.0f / 3.0f) * rsqrtf(da);              // saves RCP vs /sqrtf
  float db = Beta - (1.0f / 3.0f);
  float cb = (1.0f / 3.0f) * rsqrtf(db);

  unsigned e = bc * PIX_PER_IMG + pix;

  // -------- first attempts for gamma A and gamma B, interleaved for ILP ----
  // key chain: ek = TF(K,(0,e)); kc = split(ek)[0] = TF(ek,(0,0));
  // xk = TF(kc,(0,1)); Uk = TF(kc,(0,2)); sub = TF(xk,(0,1)).
  U2 eka = tf2x32(ka0, ka1, 0u, e);
  U2 ekb = tf2x32(kb0, kb1, 0u, e);
  U2 kca = tf2x32(eka.a, eka.b, 0u, 0u);
  U2 kcb = tf2x32(ekb.a, ekb.b, 0u, 0u);
  U2 xka = tf2x32(kca.a, kca.b, 0u, 1u);
  U2 xkb = tf2x32(kcb.a, kcb.b, 0u, 1u);
  U2 Uka = tf2x32(kca.a, kca.b, 0u, 2u);
  U2 Ukb = tf2x32(kcb.a, kcb.b, 0u, 2u);
  U2 sba = tf2x32(xka.a, xka.b, 0u, 1u);
  U2 sbb = tf2x32(xkb.a, xkb.b, 0u, 1u);

  float xa = normal_from_key(sba.a, sba.b);
  float xb = normal_from_key(sbb.a, sbb.b);
  float va = fmaf(ca, xa, 1.0f);
  float vb = fmaf(cb, xb, 1.0f);
  float Ua = u01_from_bits(bits_scalar(Uka.a, Uka.b));
  float Ub = u01_from_bits(bits_scalar(Ukb.a, Ukb.b));

  // -------- continuation loops (retries only) ------------------------------
  float logVa = mt_finish(kca.a, kca.b, xka.a, xka.b, xa, va, Ua, da, ca);
  float logVb = mt_finish(kcb.a, kcb.b, xkb.a, xkb.b, xb, vb, Ub, db, cb);

  // beta = 1/(1+exp(lgb-lga));  lgb-lga = log(db/da) + (logVb - logVa)
  // output-only arithmetic: fast intrinsics are safe here
  float z = logf(__fdividef(db, da)) + (logVb - logVa);
  out[e] = __fdividef(1.0f, 1.0f + __expf(z));
}

// ---------------------------------------------------------------------------
extern "C" void kernel_launch(void* const* d_in, const int* in_sizes, int n_in,
                              void* d_out, int out_size) {
  // find mean_control_points by size (32*3*8*8 = 6144)
  const float* mcp = (const float*)d_in[1];
  for (int i = 0; i < n_in; i++)
    if (in_sizes[i] == 6144) { mcp = (const float*)d_in[i]; break; }

  // root key = threefry_seed(1234) = (0, 1234); key_a, key_b = split(root)
  U2 ka = tf2x32(0u, 1234u, 0u, 0u);
  U2 kb = tf2x32(0u, 1234u, 0u, 1u);

  weights_kernel<<<1, 512>>>();
  dim3 grid(PIX_PER_IMG / 256, B_ * C_);
  beta_noise_kernel<<<grid, 256>>>(mcp, (float*)d_out,
                                   ka.a, ka.b, kb.a, kb.b);
}

// round 8
// speedup vs baseline: 1.8713x; 1.5939x over previous
#include <cuda_runtime.h>
#include <stdint.h>

// ============================================================================
// ControlPointBetaNoise — exact re-implementation of the JAX reference.
// R7 = R4 skeleton (record holder, at the alu-pipe compute floor) with only
// strictly instruction-reducing, decision-safe trims:
//   - rsqrtf for the MT 'c' constant
//   - output-only softmax: single logf(db/da) + __expf + __fdividef
//   - full-precision t/(sd*sd) restored (R4's verified flip set)
// Accept-test arithmetic (logf of U and V) at full precision. One pixel per
// thread; inline continuation loops with lazy key advancement.
// ============================================================================

static const unsigned B_ = 32, C_ = 3, H_ = 512, W_ = 512;
static const unsigned PIX_PER_IMG = H_ * W_;              // 262144

struct U2 { uint32_t a, b; };

__host__ __device__ __forceinline__ uint32_t rotl32(uint32_t x, int r) {
#ifdef __CUDA_ARCH__
  return __funnelshift_l(x, x, r);
#else
  return (x << r) | (x >> (32 - r));
#endif
}

// threefry2x32, 20 rounds — matches jax._src.prng.threefry2x32 exactly.
__host__ __device__ __forceinline__ U2 tf2x32(uint32_t k0, uint32_t k1,
                                              uint32_t x0, uint32_t x1) {
  uint32_t ks2 = k0 ^ k1 ^ 0x1BD11BDAu;
  x0 += k0; x1 += k1;
#define TF_RND(r) { x0 += x1; x1 = rotl32(x1, (r)); x1 ^= x0; }
  TF_RND(13) TF_RND(15) TF_RND(26) TF_RND(6)
  x0 += k1;  x1 += ks2 + 1u;
  TF_RND(17) TF_RND(29) TF_RND(16) TF_RND(24)
  x0 += ks2; x1 += k0 + 2u;
  TF_RND(13) TF_RND(15) TF_RND(26) TF_RND(6)
  x0 += k0;  x1 += k1 + 3u;
  TF_RND(17) TF_RND(29) TF_RND(16) TF_RND(24)
  x0 += k1;  x1 += ks2 + 4u;
  TF_RND(13) TF_RND(15) TF_RND(26) TF_RND(6)
  x0 += ks2; x1 += k0 + 5u;
#undef TF_RND
  return U2{x0, x1};
}

// scalar-shape random_bits(key, 32, ())  [partitionable threefry]
__device__ __forceinline__ uint32_t bits_scalar(uint32_t k0, uint32_t k1) {
  U2 r = tf2x32(k0, k1, 0u, 0u);
  return r.a ^ r.b;
}

// uniform [0,1): bitcast((bits>>9)|0x3f800000) - 1.0  (matches jax._uniform)
__device__ __forceinline__ float u01_from_bits(uint32_t bits) {
  return __uint_as_float((bits >> 9) | 0x3F800000u) - 1.0f;
}

// XLA f32 erf_inv (Giles polynomial) — what lax.erf_inv lowers to.
__device__ __forceinline__ float erfinv_f32(float x) {
  float w = -log1pf(-x * x);
  float p;
  if (w < 5.0f) {
    w -= 2.5f;
    p = 2.81022636e-08f;
    p = fmaf(p, w, 3.43273939e-07f);
    p = fmaf(p, w, -3.5233877e-06f);
    p = fmaf(p, w, -4.39150654e-06f);
    p = fmaf(p, w, 0.00021858087f);
    p = fmaf(p, w, -0.00125372503f);
    p = fmaf(p, w, -0.00417768164f);
    p = fmaf(p, w, 0.246640727f);
    p = fmaf(p, w, 1.50140941f);
  } else {
    w = sqrtf(w) - 3.0f;
    p = -0.000200214257f;
    p = fmaf(p, w, 0.000100950558f);
    p = fmaf(p, w, 0.00134934322f);
    p = fmaf(p, w, -0.00367342844f);
    p = fmaf(p, w, 0.00573950773f);
    p = fmaf(p, w, -0.0076224613f);
    p = fmaf(p, w, 0.00943887047f);
    p = fmaf(p, w, 1.00167406f);
    p = fmaf(p, w, 2.83297682f);
  }
  return p * x;
}

// jax.random.normal: u = uniform(key, lo=nextafter(-1,0), hi=1); sqrt(2)*erfinv(u)
__device__ __forceinline__ float normal_from_key(uint32_t k0, uint32_t k1) {
  uint32_t bits = bits_scalar(k0, k1);
  float f = u01_from_bits(bits);
  const float LO = __uint_as_float(0xBF7FFFFFu);  // nextafter(-1,0)
  float u = fmaxf(LO, f * 2.0f + LO);
  return 1.41421356237f * erfinv_f32(u);
}

// ---------------------------------------------------------------------------
// Bicubic weight table: jax.image.resize "bicubic" (Keys a=-0.5, renormalized,
// half-pixel sampling). Identical for H and W (8 -> 512).
// ---------------------------------------------------------------------------
__device__ float g_w[512][8];

__global__ void weights_kernel() {
  int j = threadIdx.x;  // 0..511
  float s = (j + 0.5f) * (1.0f / 64.0f) - 0.5f;
  float w[8]; float sum = 0.0f;
#pragma unroll
  for (int i = 0; i < 8; i++) {
    float x = fabsf(s - (float)i);
    float out = ((1.5f * x - 2.5f) * x) * x + 1.0f;
    if (x >= 1.0f) out = ((-0.5f * x + 2.5f) * x - 4.0f) * x + 2.0f;
    if (x >= 2.0f) out = 0.0f;
    w[i] = out; sum += out;
  }
#pragma unroll
  for (int i = 0; i < 8; i++) g_w[j][i] = w[i] / sum;
}

// ---------------------------------------------------------------------------
// Marsaglia–Tsang continuation loop: resumes from an already-computed first
// attempt (outer key kl, inner key xk, draw x/v, uniform U). Lazily advances
// keys only when a retry actually happens — no replayed threefry work.
// Returns log(V) of the accepted draw.
// ---------------------------------------------------------------------------
__device__ __forceinline__ float mt_finish(uint32_t kl0, uint32_t kl1,
                                           uint32_t xk0, uint32_t xk1,
                                           float x, float v, float U,
                                           float d, float c) {
  for (;;) {
    // inner rejection: redraw normal until v > 0 (advance inner key lazily)
    while (v <= 0.0f) {
      U2 nxt = tf2x32(xk0, xk1, 0u, 0u);
      xk0 = nxt.a; xk1 = nxt.b;
      U2 sub = tf2x32(xk0, xk1, 0u, 1u);
      x = normal_from_key(sub.a, sub.b);
      v = fmaf(c, x, 1.0f);
    }
    float X = x * x;
    float V = (v * v) * v;
    float lV = logf(V);            // decision-critical: full precision
    bool rej = (U >= 1.0f - 0.0331f * (X * X)) &&
               (logf(U) >= 0.5f * X + d * (1.0f - V + lV));
    if (!rej) return lV;
    // outer rejection: advance outer key lazily, draw a fresh attempt
    U2 nk = tf2x32(kl0, kl1, 0u, 0u);
    kl0 = nk.a; kl1 = nk.b;
    U2 xk = tf2x32(kl0, kl1, 0u, 1u);
    xk0 = xk.a; xk1 = xk.b;
    U2 Uk = tf2x32(kl0, kl1, 0u, 2u);
    U2 sub = tf2x32(xk0, xk1, 0u, 1u);
    x = normal_from_key(sub.a, sub.b);
    v = fmaf(c, x, 1.0f);
    U = u01_from_bits(bits_scalar(Uk.a, Uk.b));
  }
}

// ---------------------------------------------------------------------------
// Main kernel: one thread per output pixel.
// ---------------------------------------------------------------------------
__global__ void __launch_bounds__(256)
beta_noise_kernel(const float* __restrict__ mcp, float* __restrict__ out,
                  uint32_t ka0, uint32_t ka1, uint32_t kb0, uint32_t kb1) {
  __shared__ float G[64];
  unsigned bc = blockIdx.y;
  if (threadIdx.x < 64)
    G[threadIdx.x] = mcp[bc * 64u + threadIdx.x] * 0.9f + 0.05f;
  __syncthreads();

  unsigned pix = blockIdx.x * 256u + threadIdx.x;
  unsigned y = pix >> 9, x = pix & 511u;

  // separable bicubic: m = wy^T * G * wx
  const float4* wx4 = reinterpret_cast<const float4*>(g_w[x]);
  float4 wxa = wx4[0], wxb = wx4[1];
  const float4* wy4 = reinterpret_cast<const float4*>(g_w[y]);
  float4 wya = wy4[0], wyb = wy4[1];
  float wyv[8] = {wya.x, wya.y, wya.z, wya.w, wyb.x, wyb.y, wyb.z, wyb.w};

  float m = 0.0f;
#pragma unroll
  for (int i = 0; i < 8; i++) {
    const float* gr = &G[i * 8];
    float gy = wxa.x * gr[0] + wxa.y * gr[1] + wxa.z * gr[2] + wxa.w * gr[3]
             + wxb.x * gr[4] + wxb.y * gr[5] + wxb.z * gr[6] + wxb.w * gr[7];
    m += wyv[i] * gy;
  }

  m = fminf(fmaxf(m, 0.05f), 0.95f);
  float t  = m * (1.0f - m);
  float sd = t - 1e-6f;
  float V_ = t / (sd * sd) - 1.0f;                    // full precision (R4)
  float Alpha = fmaxf(m * V_, 0.0f) + 1e-6f;          // always >= 1.0027
  float Beta  = fmaxf((1.0f - m) * V_, 0.0f) + 1e-6f; // always >= 1.0027

  // MT constants (boost branch provably dead: alpha >= 1)
  float da = Alpha - (1.0f / 3.0f);
  float ca = (1.0f / 3.0f) * rsqrtf(da);
  float db = Beta - (1.0f / 3.0f);
  float cb = (1.0f / 3.0f) * rsqrtf(db);

  unsigned e = bc * PIX_PER_IMG + pix;

  // -------- first attempts for gamma A and gamma B, interleaved for ILP ----
  // key chain: ek = TF(K,(0,e)); kc = split(ek)[0] = TF(ek,(0,0));
  // xk = TF(kc,(0,1)); Uk = TF(kc,(0,2)); sub = TF(xk,(0,1)).
  U2 eka = tf2x32(ka0, ka1, 0u, e);
  U2 ekb = tf2x32(kb0, kb1, 0u, e);
  U2 kca = tf2x32(eka.a, eka.b, 0u, 0u);
  U2 kcb = tf2x32(ekb.a, ekb.b, 0u, 0u);
  U2 xka = tf2x32(kca.a, kca.b, 0u, 1u);
  U2 xkb = tf2x32(kcb.a, kcb.b, 0u, 1u);
  U2 Uka = tf2x32(kca.a, kca.b, 0u, 2u);
  U2 Ukb = tf2x32(kcb.a, kcb.b, 0u, 2u);
  U2 sba = tf2x32(xka.a, xka.b, 0u, 1u);
  U2 sbb = tf2x32(xkb.a, xkb.b, 0u, 1u);

  float xa = normal_from_key(sba.a, sba.b);
  float xb = normal_from_key(sbb.a, sbb.b);
  float va = fmaf(ca, xa, 1.0f);
  float vb = fmaf(cb, xb, 1.0f);
  float Ua = u01_from_bits(bits_scalar(Uka.a, Uka.b));
  float Ub = u01_from_bits(bits_scalar(Ukb.a, Ukb.b));

  // -------- continuation loops (retries only) ------------------------------
  float logVa = mt_finish(kca.a, kca.b, xka.a, xka.b, xa, va, Ua, da, ca);
  float logVb = mt_finish(kcb.a, kcb.b, xkb.a, xkb.b, xb, vb, Ub, db, cb);

  // beta = 1/(1+exp(lgb-lga));  lgb-lga = log(db/da) + (logVb - logVa)
  // output-only arithmetic: fast intrinsics are safe here
  float z = logf(__fdividef(db, da)) + (logVb - logVa);
  out[e] = __fdividef(1.0f, 1.0f + __expf(z));
}

// ---------------------------------------------------------------------------
extern "C" void kernel_launch(void* const* d_in, const int* in_sizes, int n_in,
                              void* d_out, int out_size) {
  // find mean_control_points by size (32*3*8*8 = 6144)
  const float* mcp = (const float*)d_in[1];
  for (int i = 0; i < n_in; i++)
    if (in_sizes[i] == 6144) { mcp = (const float*)d_in[i]; break; }

  // root key = threefry_seed(1234) = (0, 1234); key_a, key_b = split(root)
  U2 ka = tf2x32(0u, 1234u, 0u, 0u);
  U2 kb = tf2x32(0u, 1234u, 0u, 1u);

  weights_kernel<<<1, 512>>>();
  dim3 grid(PIX_PER_IMG / 256, B_ * C_);
  beta_noise_kernel<<<grid, 256>>>(mcp, (float*)d_out,
                                   ka.a, ka.b, kb.a, kb.b);
}

// round 9
// speedup vs baseline: 2.5067x; 1.3395x over previous
#include <cuda_runtime.h>
#include <stdint.h>

// ============================================================================
// ControlPointBetaNoise — exact re-implementation of the JAX reference.
// R8: two-phase retry compaction.
//   Phase 1: straight-line first attempts for both gammas; ~93% of elements
//            accept both and write output. Failures push element idx to a
//            global queue (no retry loops in the hot kernel -> no divergence).
//   Phase 2: grid-stride dense kernel replays queued elements from scratch
//            (bit-identical key chain) with full rejection loops.
// Output for every element is bit-identical to the R7 kernel.
// ============================================================================

static const unsigned B_ = 32, C_ = 3, H_ = 512, W_ = 512;
static const unsigned PIX_PER_IMG = H_ * W_;              // 262144 = 1<<18

struct U2 { uint32_t a, b; };

__host__ __device__ __forceinline__ uint32_t rotl32(uint32_t x, int r) {
#ifdef __CUDA_ARCH__
  return __funnelshift_l(x, x, r);
#else
  return (x << r) | (x >> (32 - r));
#endif
}

// threefry2x32, 20 rounds — matches jax._src.prng.threefry2x32 exactly.
__host__ __device__ __forceinline__ U2 tf2x32(uint32_t k0, uint32_t k1,
                                              uint32_t x0, uint32_t x1) {
  uint32_t ks2 = k0 ^ k1 ^ 0x1BD11BDAu;
  x0 += k0; x1 += k1;
#define TF_RND(r) { x0 += x1; x1 = rotl32(x1, (r)); x1 ^= x0; }
  TF_RND(13) TF_RND(15) TF_RND(26) TF_RND(6)
  x0 += k1;  x1 += ks2 + 1u;
  TF_RND(17) TF_RND(29) TF_RND(16) TF_RND(24)
  x0 += ks2; x1 += k0 + 2u;
  TF_RND(13) TF_RND(15) TF_RND(26) TF_RND(6)
  x0 += k0;  x1 += k1 + 3u;
  TF_RND(17) TF_RND(29) TF_RND(16) TF_RND(24)
  x0 += k1;  x1 += ks2 + 4u;
  TF_RND(13) TF_RND(15) TF_RND(26) TF_RND(6)
  x0 += ks2; x1 += k0 + 5u;
#undef TF_RND
  return U2{x0, x1};
}

__device__ __forceinline__ uint32_t bits_scalar(uint32_t k0, uint32_t k1) {
  U2 r = tf2x32(k0, k1, 0u, 0u);
  return r.a ^ r.b;
}

__device__ __forceinline__ float u01_from_bits(uint32_t bits) {
  return __uint_as_float((bits >> 9) | 0x3F800000u) - 1.0f;
}

// XLA f32 erf_inv (Giles polynomial) — what lax.erf_inv lowers to.
__device__ __forceinline__ float erfinv_f32(float x) {
  float w = -log1pf(-x * x);
  float p;
  if (w < 5.0f) {
    w -= 2.5f;
    p = 2.81022636e-08f;
    p = fmaf(p, w, 3.43273939e-07f);
    p = fmaf(p, w, -3.5233877e-06f);
    p = fmaf(p, w, -4.39150654e-06f);
    p = fmaf(p, w, 0.00021858087f);
    p = fmaf(p, w, -0.00125372503f);
    p = fmaf(p, w, -0.00417768164f);
    p = fmaf(p, w, 0.246640727f);
    p = fmaf(p, w, 1.50140941f);
  } else {
    w = sqrtf(w) - 3.0f;
    p = -0.000200214257f;
    p = fmaf(p, w, 0.000100950558f);
    p = fmaf(p, w, 0.00134934322f);
    p = fmaf(p, w, -0.00367342844f);
    p = fmaf(p, w, 0.00573950773f);
    p = fmaf(p, w, -0.0076224613f);
    p = fmaf(p, w, 0.00943887047f);
    p = fmaf(p, w, 1.00167406f);
    p = fmaf(p, w, 2.83297682f);
  }
  return p * x;
}

__device__ __forceinline__ float normal_from_key(uint32_t k0, uint32_t k1) {
  uint32_t bits = bits_scalar(k0, k1);
  float f = u01_from_bits(bits);
  const float LO = __uint_as_float(0xBF7FFFFFu);  // nextafter(-1,0)
  float u = fmaxf(LO, f * 2.0f + LO);
  return 1.41421356237f * erfinv_f32(u);
}

// ---------------------------------------------------------------------------
// Bicubic weight table (jax.image.resize "bicubic", Keys a=-0.5, renormalized)
// ---------------------------------------------------------------------------
__device__ float g_w[512][8];

__global__ void weights_kernel() {
  int j = threadIdx.x;  // 0..511
  float s = (j + 0.5f) * (1.0f / 64.0f) - 0.5f;
  float w[8]; float sum = 0.0f;
#pragma unroll
  for (int i = 0; i < 8; i++) {
    float x = fabsf(s - (float)i);
    float out = ((1.5f * x - 2.5f) * x) * x + 1.0f;
    if (x >= 1.0f) out = ((-0.5f * x + 2.5f) * x - 4.0f) * x + 2.0f;
    if (x >= 2.0f) out = 0.0f;
    w[i] = out; sum += out;
  }
#pragma unroll
  for (int i = 0; i < 8; i++) g_w[j][i] = w[i] / sum;
}

// ---------------------------------------------------------------------------
// Retry queue (device scratch; allocation-free per harness rules).
// ---------------------------------------------------------------------------
static const unsigned QCAP = 1u << 23;  // 8.4M entries (expected ~1.8M)
__device__ uint32_t g_queue[QCAP];
__device__ uint32_t g_count;

__global__ void reset_kernel() { g_count = 0u; }

// ---------------------------------------------------------------------------
// Marsaglia–Tsang continuation loop (resumes from computed first attempt).
// Returns log(V) of the accepted draw. Decision-critical logf at full prec.
// ---------------------------------------------------------------------------
__device__ __forceinline__ float mt_finish(uint32_t kl0, uint32_t kl1,
                                           uint32_t xk0, uint32_t xk1,
                                           float x, float v, float U,
                                           float d, float c) {
  for (;;) {
    while (v <= 0.0f) {
      U2 nxt = tf2x32(xk0, xk1, 0u, 0u);
      xk0 = nxt.a; xk1 = nxt.b;
      U2 sub = tf2x32(xk0, xk1, 0u, 1u);
      x = normal_from_key(sub.a, sub.b);
      v = fmaf(c, x, 1.0f);
    }
    float X = x * x;
    float V = (v * v) * v;
    float lV = logf(V);
    bool rej = (U >= 1.0f - 0.0331f * (X * X)) &&
               (logf(U) >= 0.5f * X + d * (1.0f - V + lV));
    if (!rej) return lV;
    U2 nk = tf2x32(kl0, kl1, 0u, 0u);
    kl0 = nk.a; kl1 = nk.b;
    U2 xk = tf2x32(kl0, kl1, 0u, 1u);
    xk0 = xk.a; xk1 = xk.b;
    U2 Uk = tf2x32(kl0, kl1, 0u, 2u);
    U2 sub = tf2x32(xk0, xk1, 0u, 1u);
    x = normal_from_key(sub.a, sub.b);
    v = fmaf(c, x, 1.0f);
    U = u01_from_bits(bits_scalar(Uk.a, Uk.b));
  }
}

// ---------------------------------------------------------------------------
// Shared per-element setup: alpha/beta params from bicubic mean.
// ---------------------------------------------------------------------------
__device__ __forceinline__ void elem_params(float m, float& da, float& ca,
                                            float& db, float& cb) {
  m = fminf(fmaxf(m, 0.05f), 0.95f);
  float t  = m * (1.0f - m);
  float sd = t - 1e-6f;
  float V_ = t / (sd * sd) - 1.0f;                    // full precision
  float Alpha = fmaxf(m * V_, 0.0f) + 1e-6f;          // >= 1.0027
  float Beta  = fmaxf((1.0f - m) * V_, 0.0f) + 1e-6f; // >= 1.0027
  da = Alpha - (1.0f / 3.0f);
  ca = (1.0f / 3.0f) * rsqrtf(da);
  db = Beta - (1.0f / 3.0f);
  cb = (1.0f / 3.0f) * rsqrtf(db);
}

// First-attempt state for one gamma.
struct FA { U2 kc, xk; float x, v, U; };

__device__ __forceinline__ FA first_attempt(uint32_t K0, uint32_t K1,
                                            uint32_t e, float c) {
  FA f;
  U2 ek = tf2x32(K0, K1, 0u, e);
  f.kc = tf2x32(ek.a, ek.b, 0u, 0u);
  f.xk = tf2x32(f.kc.a, f.kc.b, 0u, 1u);
  U2 Uk = tf2x32(f.kc.a, f.kc.b, 0u, 2u);
  U2 sb = tf2x32(f.xk.a, f.xk.b, 0u, 1u);
  f.x = normal_from_key(sb.a, sb.b);
  f.v = fmaf(c, f.x, 1.0f);
  f.U = u01_from_bits(bits_scalar(Uk.a, Uk.b));
  return f;
}

// Accept test on a first attempt. Returns true + logV on acceptance.
__device__ __forceinline__ bool try_accept(const FA& f, float d, float& lV) {
  float X = f.x * f.x;
  float V = (f.v * f.v) * f.v;
  float l = logf(V);
  bool rej = (f.U >= 1.0f - 0.0331f * (X * X)) &&
             (logf(f.U) >= 0.5f * X + d * (1.0f - V + l));
  lV = l;
  return (f.v > 0.0f) && !rej;
}

// ---------------------------------------------------------------------------
// Phase 1: straight-line fast path; failures enqueued.
// ---------------------------------------------------------------------------
__global__ void __launch_bounds__(256)
phase1_kernel(const float* __restrict__ mcp, float* __restrict__ out,
              uint32_t ka0, uint32_t ka1, uint32_t kb0, uint32_t kb1) {
  __shared__ float G[64];
  unsigned bc = blockIdx.y;
  if (threadIdx.x < 64)
    G[threadIdx.x] = mcp[bc * 64u + threadIdx.x] * 0.9f + 0.05f;
  __syncthreads();

  unsigned pix = blockIdx.x * 256u + threadIdx.x;
  unsigned y = pix >> 9, x = pix & 511u;

  const float4* wx4 = reinterpret_cast<const float4*>(g_w[x]);
  float4 wxa = wx4[0], wxb = wx4[1];
  const float4* wy4 = reinterpret_cast<const float4*>(g_w[y]);
  float4 wya = wy4[0], wyb = wy4[1];
  float wyv[8] = {wya.x, wya.y, wya.z, wya.w, wyb.x, wyb.y, wyb.z, wyb.w};

  float m = 0.0f;
#pragma unroll
  for (int i = 0; i < 8; i++) {
    const float* gr = &G[i * 8];
    float gy = wxa.x * gr[0] + wxa.y * gr[1] + wxa.z * gr[2] + wxa.w * gr[3]
             + wxb.x * gr[4] + wxb.y * gr[5] + wxb.z * gr[6] + wxb.w * gr[7];
    m += wyv[i] * gy;
  }

  float da, ca, db, cb;
  elem_params(m, da, ca, db, cb);

  unsigned e = bc * PIX_PER_IMG + pix;

  FA fa = first_attempt(ka0, ka1, e, ca);
  FA fb = first_attempt(kb0, kb1, e, cb);

  float lVa, lVb;
  bool okA = try_accept(fa, da, lVa);
  bool okB = try_accept(fb, db, lVb);

  if (okA && okB) {
    float z = logf(__fdividef(db, da)) + (lVb - lVa);
    out[e] = __fdividef(1.0f, 1.0f + __expf(z));
  } else {
    uint32_t slot = atomicAdd(&g_count, 1u);
    if (slot < QCAP) {
      g_queue[slot] = e;
    } else {
      // overflow fallback (practically unreachable): resolve inline
      float logVa = okA ? lVa
                        : mt_finish(fa.kc.a, fa.kc.b, fa.xk.a, fa.xk.b,
                                    fa.x, fa.v, fa.U, da, ca);
      float logVb = okB ? lVb
                        : mt_finish(fb.kc.a, fb.kc.b, fb.xk.a, fb.xk.b,
                                    fb.x, fb.v, fb.U, db, cb);
      float z = logf(__fdividef(db, da)) + (logVb - logVa);
      out[e] = __fdividef(1.0f, 1.0f + __expf(z));
    }
  }
}

// ---------------------------------------------------------------------------
// Phase 2: dense replay of queued elements (bit-identical key chains).
// ---------------------------------------------------------------------------
__global__ void __launch_bounds__(256)
phase2_kernel(const float* __restrict__ mcp, float* __restrict__ out,
              uint32_t ka0, uint32_t ka1, uint32_t kb0, uint32_t kb1) {
  uint32_t count = min(g_count, QCAP);
  unsigned stride = gridDim.x * 256u;
  for (uint32_t i = blockIdx.x * 256u + threadIdx.x; i < count; i += stride) {
    unsigned e = g_queue[i];
    unsigned bc = e >> 18;           // / PIX_PER_IMG
    unsigned pix = e & (PIX_PER_IMG - 1u);
    unsigned y = pix >> 9, x = pix & 511u;

    // recompute bicubic mean from global (tiny, L2-resident)
    const float* Gm = mcp + bc * 64u;
    const float4* wx4 = reinterpret_cast<const float4*>(g_w[x]);
    float4 wxa = wx4[0], wxb = wx4[1];
    const float4* wy4 = reinterpret_cast<const float4*>(g_w[y]);
    float4 wya = wy4[0], wyb = wy4[1];
    float wyv[8] = {wya.x, wya.y, wya.z, wya.w, wyb.x, wyb.y, wyb.z, wyb.w};
    float m = 0.0f;
#pragma unroll
    for (int r = 0; r < 8; r++) {
      const float* gr = Gm + r * 8;
      float gy = wxa.x * __ldg(gr+0) + wxa.y * __ldg(gr+1)
               + wxa.z * __ldg(gr+2) + wxa.w * __ldg(gr+3)
               + wxb.x * __ldg(gr+4) + wxb.y * __ldg(gr+5)
               + wxb.z * __ldg(gr+6) + wxb.w * __ldg(gr+7);
      m += wyv[r] * gy;
    }
    m = fmaf(m, 0.9f, 0.05f);

    float da, ca, db, cb;
    elem_params(m, da, ca, db, cb);

    FA fa = first_attempt(ka0, ka1, e, ca);
    FA fb = first_attempt(kb0, kb1, e, cb);

    float logVa = mt_finish(fa.kc.a, fa.kc.b, fa.xk.a, fa.xk.b,
                            fa.x, fa.v, fa.U, da, ca);
    float logVb = mt_finish(fb.kc.a, fb.kc.b, fb.xk.a, fb.xk.b,
                            fb.x, fb.v, fb.U, db, cb);

    float z = logf(__fdividef(db, da)) + (logVb - logVa);
    out[e] = __fdividef(1.0f, 1.0f + __expf(z));
  }
}

// ---------------------------------------------------------------------------
extern "C" void kernel_launch(void* const* d_in, const int* in_sizes, int n_in,
                              void* d_out, int out_size) {
  const float* mcp = (const float*)d_in[1];
  for (int i = 0; i < n_in; i++)
    if (in_sizes[i] == 6144) { mcp = (const float*)d_in[i]; break; }

  // root key = threefry_seed(1234) = (0, 1234); key_a, key_b = split(root)
  U2 ka = tf2x32(0u, 1234u, 0u, 0u);
  U2 kb = tf2x32(0u, 1234u, 0u, 1u);

  weights_kernel<<<1, 512>>>();
  reset_kernel<<<1, 1>>>();
  dim3 grid(PIX_PER_IMG / 256, B_ * C_);
  phase1_kernel<<<grid, 256>>>(mcp, (float*)d_out, ka.a, ka.b, kb.a, kb.b);
  phase2_kernel<<<1024, 256>>>(mcp, (float*)d_out, ka.a, ka.b, kb.a, kb.b);
}